// round 1
// baseline (speedup 1.0000x reference)
#include <cuda_runtime.h>
#include <cuda_bf16.h>

// SphereTracingRenderer: 64-iter sphere trace + 3->128->3 MLP color, masked.
// Strategy: 2 rays per thread packed into f32x2 lanes (HW FFMA2 via PTX),
// weights pre-duplicated in shared memory for pair-broadcast LDS.128 loads.

#define N_ITERS 64
#define HIDDEN 128
#define SDF_EPS 1e-4f

typedef unsigned long long u64;

__device__ __forceinline__ u64 pk(float a, float b) {
    u64 r; asm("mov.b64 %0,{%1,%2};" : "=l"(r) : "f"(a), "f"(b)); return r;
}
__device__ __forceinline__ void upk(u64 v, float& a, float& b) {
    asm("mov.b64 {%0,%1},%2;" : "=f"(a), "=f"(b) : "l"(v));
}
__device__ __forceinline__ u64 fma2(u64 a, u64 b, u64 c) {
    u64 d; asm("fma.rn.f32x2 %0,%1,%2,%3;" : "=l"(d) : "l"(a), "l"(b), "l"(c)); return d;
}
__device__ __forceinline__ u64 mul2(u64 a, u64 b) {
    u64 d; asm("mul.rn.f32x2 %0,%1,%2;" : "=l"(d) : "l"(a), "l"(b)); return d;
}
__device__ __forceinline__ u64 add2(u64 a, u64 b) {
    u64 d; asm("add.rn.f32x2 %0,%1,%2;" : "=l"(d) : "l"(a), "l"(b)); return d;
}
__device__ __forceinline__ float sqap(float x) {
    float r; asm("sqrt.approx.f32 %0,%1;" : "=f"(r) : "f"(x)); return r;
}
__device__ __forceinline__ float rcpa(float x) {
    float r; asm("rcp.approx.f32 %0,%1;" : "=f"(r) : "f"(x)); return r;
}
__device__ __forceinline__ float sgm(float x) {
    // sigmoid(x) = 1 / (1 + exp(-x)); __expf -> MUFU.EX2 fast path
    return rcpa(1.0f + __expf(-x));
}

__global__ void __launch_bounds__(256)
sphere_trace_kernel(const float* __restrict__ origins,
                    const float* __restrict__ directions,
                    const float* __restrict__ center,
                    const float* __restrict__ radius,
                    const float* __restrict__ W1,
                    const float* __restrict__ b1,
                    const float* __restrict__ W2,
                    const float* __restrict__ b2,
                    float* __restrict__ out,
                    int n_pairs)
{
    // Duplicated weight layout: per hidden unit j:
    //   sW1[2j]   = {w1x,w1x, w1y,w1y}   sW1[2j+1] = {w1z,w1z, b1,b1}
    //   sW2[2j]   = {w20,w20, w21,w21}   sW2[2j+1] = {w22,w22, 0,0}
    __shared__ ulonglong2 sW1[2 * HIDDEN];
    __shared__ ulonglong2 sW2[2 * HIDDEN];

    int t = threadIdx.x;
    if (t < HIDDEN) {
        float w1x = W1[t], w1y = W1[HIDDEN + t], w1z = W1[2 * HIDDEN + t], bb = b1[t];
        float* p = (float*)&sW1[2 * t];
        p[0] = w1x; p[1] = w1x; p[2] = w1y; p[3] = w1y;
        p[4] = w1z; p[5] = w1z; p[6] = bb;  p[7] = bb;
        float u = W2[3 * t], v = W2[3 * t + 1], w = W2[3 * t + 2];
        float* q = (float*)&sW2[2 * t];
        q[0] = u; q[1] = u; q[2] = v; q[3] = v;
        q[4] = w; q[5] = w; q[6] = 0.f; q[7] = 0.f;
    }
    __syncthreads();

    int i = blockIdx.x * blockDim.x + t;   // pair index: rays 2i, 2i+1
    if (i >= n_pairs) return;

    float cx = center[0], cy = center[1], cz = center[2];
    float rad = radius[0];

    // Load 2 rays (6 floats each) as 3 float2 each, 8B-aligned, coalesced.
    const float2* og = (const float2*)origins;
    const float2* dg = (const float2*)directions;
    float2 oa = og[3 * i], ob = og[3 * i + 1], oc = og[3 * i + 2];
    float2 da = dg[3 * i], db = dg[3 * i + 1], dc = dg[3 * i + 2];
    // ray0 = (a.x, a.y, b.x); ray1 = (b.y, c.x, c.y)

    // q = origin - center (trace in centered coords)
    u64 qx = pk(oa.x - cx, ob.y - cx);
    u64 qy = pk(oa.y - cy, oc.x - cy);
    u64 qz = pk(ob.x - cz, oc.y - cz);
    u64 vx = pk(da.x, db.y);
    u64 vy = pk(da.y, dc.x);
    u64 vz = pk(db.x, dc.y);

    float s0 = 0.f, s1 = 0.f;   // last-iteration sdf (pre-update), for the mask
    #pragma unroll 8
    for (int it = 0; it < N_ITERS; ++it) {
        u64 n2 = fma2(qx, qx, fma2(qy, qy, mul2(qz, qz)));
        float n0, n1; upk(n2, n0, n1);
        s0 = sqap(n0) - rad;
        s1 = sqap(n1) - rad;
        u64 sdf2 = pk(s0, s1);
        qx = fma2(sdf2, vx, qx);
        qy = fma2(sdf2, vy, qy);
        qz = fma2(sdf2, vz, qz);
    }
    bool m0 = s0 < SDF_EPS;
    bool m1 = s1 < SDF_EPS;

    // points = q + center
    u64 px = add2(qx, pk(cx, cx));
    u64 py = add2(qy, pk(cy, cy));
    u64 pz = add2(qz, pk(cz, cz));

    float bo0 = b2[0], bo1 = b2[1], bo2 = b2[2];
    u64 a0 = pk(bo0, bo0);
    u64 a1 = pk(bo1, bo1);
    u64 a2 = pk(bo2, bo2);

    #pragma unroll 8
    for (int j = 0; j < HIDDEN; ++j) {
        ulonglong2 wA = sW1[2 * j];       // {w1x,w1x},{w1y,w1y}
        ulonglong2 wB = sW1[2 * j + 1];   // {w1z,w1z},{b,b}
        u64 h = fma2(px, wA.x, fma2(py, wA.y, fma2(pz, wB.x, wB.y)));
        float h0, h1; upk(h, h0, h1);
        h = pk(fmaxf(h0, 0.f), fmaxf(h1, 0.f));
        ulonglong2 uA = sW2[2 * j];       // {w20,w20},{w21,w21}
        ulonglong2 uB = sW2[2 * j + 1];   // {w22,w22},{0,0}
        a0 = fma2(h, uA.x, a0);
        a1 = fma2(h, uA.y, a1);
        a2 = fma2(h, uB.x, a2);
    }

    float x00, x10, x01, x11, x02, x12;
    upk(a0, x00, x10);
    upk(a1, x01, x11);
    upk(a2, x02, x12);

    float r0c0 = m0 ? sgm(x00) : 0.f;
    float r0c1 = m0 ? sgm(x01) : 0.f;
    float r0c2 = m0 ? sgm(x02) : 0.f;
    float r1c0 = m1 ? sgm(x10) : 0.f;
    float r1c1 = m1 ? sgm(x11) : 0.f;
    float r1c2 = m1 ? sgm(x12) : 0.f;

    float2* o2 = (float2*)out;
    o2[3 * i]     = make_float2(r0c0, r0c1);
    o2[3 * i + 1] = make_float2(r0c2, r1c0);
    o2[3 * i + 2] = make_float2(r1c1, r1c2);
}

extern "C" void kernel_launch(void* const* d_in, const int* in_sizes, int n_in,
                              void* d_out, int out_size) {
    const float* origins    = (const float*)d_in[0];
    const float* directions = (const float*)d_in[1];
    const float* center     = (const float*)d_in[2];
    const float* radius     = (const float*)d_in[3];
    const float* W1         = (const float*)d_in[4];
    const float* b1         = (const float*)d_in[5];
    const float* W2         = (const float*)d_in[6];
    const float* b2         = (const float*)d_in[7];
    float* out = (float*)d_out;

    int n_rays = in_sizes[0] / 3;
    int n_pairs = n_rays / 2;
    int block = 256;
    int grid = (n_pairs + block - 1) / block;
    sphere_trace_kernel<<<grid, block>>>(origins, directions, center, radius,
                                         W1, b1, W2, b2, out, n_pairs);
}

// round 2
// speedup vs baseline: 1.5416x; 1.5416x over previous
#include <cuda_runtime.h>
#include <cuda_bf16.h>

// SphereTracingRenderer: 64-iter sphere trace + 3->128->3 MLP color, masked.
// 4 rays per thread as two f32x2 packed pairs (HW FFMA2 via PTX).
// Weights pre-duplicated in shared; each weight LDS serves 4 rays.
// Warp-coherent early exit in the trace using SDF monotonicity.

#define N_BLKS 16           // 16 blocks x 4 iters = 64
#define HIDDEN 128
#define SDF_EPS 1e-4f
#define EPS_HIT 5e-5f       // s < this => final s63 < SDF_EPS (monotone decrease)
#define EPS_MISS 2e-4f      // s increasing and > this => final s63 > SDF_EPS

typedef unsigned long long u64;

__device__ __forceinline__ u64 pk(float a, float b) {
    u64 r; asm("mov.b64 %0,{%1,%2};" : "=l"(r) : "f"(a), "f"(b)); return r;
}
__device__ __forceinline__ void upk(u64 v, float& a, float& b) {
    asm("mov.b64 {%0,%1},%2;" : "=f"(a), "=f"(b) : "l"(v));
}
__device__ __forceinline__ u64 fma2(u64 a, u64 b, u64 c) {
    u64 d; asm("fma.rn.f32x2 %0,%1,%2,%3;" : "=l"(d) : "l"(a), "l"(b), "l"(c)); return d;
}
__device__ __forceinline__ u64 mul2(u64 a, u64 b) {
    u64 d; asm("mul.rn.f32x2 %0,%1,%2;" : "=l"(d) : "l"(a), "l"(b)); return d;
}
__device__ __forceinline__ u64 add2(u64 a, u64 b) {
    u64 d; asm("add.rn.f32x2 %0,%1,%2;" : "=l"(d) : "l"(a), "l"(b)); return d;
}
__device__ __forceinline__ float sqap(float x) {
    float r; asm("sqrt.approx.f32 %0,%1;" : "=f"(r) : "f"(x)); return r;
}
__device__ __forceinline__ float rcpa(float x) {
    float r; asm("rcp.approx.f32 %0,%1;" : "=f"(r) : "f"(x)); return r;
}
__device__ __forceinline__ float sgm(float x) {
    return rcpa(1.0f + __expf(-x));
}
__device__ __forceinline__ u64 relu2(u64 h) {
    float h0, h1; upk(h, h0, h1);
    return pk(fmaxf(h0, 0.f), fmaxf(h1, 0.f));
}

__global__ void __launch_bounds__(256)
sphere_trace_kernel(const float* __restrict__ origins,
                    const float* __restrict__ directions,
                    const float* __restrict__ center,
                    const float* __restrict__ radius,
                    const float* __restrict__ W1,
                    const float* __restrict__ b1,
                    const float* __restrict__ W2,
                    const float* __restrict__ b2,
                    float* __restrict__ out,
                    int n_quads)
{
    // Duplicated weight layout per hidden unit j:
    //   sW1[2j]   = {w1x,w1x, w1y,w1y}   sW1[2j+1] = {w1z,w1z, b1,b1}
    //   sW2[2j]   = {w20,w20, w21,w21}   sW2[2j+1] = {w22,w22, 0,0}
    __shared__ ulonglong2 sW1[2 * HIDDEN];
    __shared__ ulonglong2 sW2[2 * HIDDEN];

    int t = threadIdx.x;
    if (t < HIDDEN) {
        float w1x = W1[t], w1y = W1[HIDDEN + t], w1z = W1[2 * HIDDEN + t], bb = b1[t];
        float* p = (float*)&sW1[2 * t];
        p[0] = w1x; p[1] = w1x; p[2] = w1y; p[3] = w1y;
        p[4] = w1z; p[5] = w1z; p[6] = bb;  p[7] = bb;
        float u = W2[3 * t], v = W2[3 * t + 1], w = W2[3 * t + 2];
        float* q = (float*)&sW2[2 * t];
        q[0] = u; q[1] = u; q[2] = v; q[3] = v;
        q[4] = w; q[5] = w; q[6] = 0.f; q[7] = 0.f;
    }
    __syncthreads();

    int i = blockIdx.x * blockDim.x + t;   // quad index: rays 4i .. 4i+3
    if (i >= n_quads) return;

    float cx = center[0], cy = center[1], cz = center[2];
    float rad = radius[0];

    // Load 4 rays (12 floats) as 3 float4, fully coalesced.
    const float4* og = (const float4*)origins;
    const float4* dg = (const float4*)directions;
    float4 A = og[3 * i], B = og[3 * i + 1], C = og[3 * i + 2];
    float4 DA = dg[3 * i], DB = dg[3 * i + 1], DC = dg[3 * i + 2];
    // ray0=(A.x,A.y,A.z) ray1=(A.w,B.x,B.y) ray2=(B.z,B.w,C.x) ray3=(C.y,C.z,C.w)

    // Pair P = rays {0,1}, pair Q = rays {2,3}; trace in centered coords q = p - c.
    u64 qxP = pk(A.x - cx, A.w - cx);
    u64 qyP = pk(A.y - cy, B.x - cy);
    u64 qzP = pk(A.z - cz, B.y - cz);
    u64 qxQ = pk(B.z - cx, C.y - cx);
    u64 qyQ = pk(B.w - cy, C.z - cy);
    u64 qzQ = pk(C.x - cz, C.w - cz);
    u64 vxP = pk(DA.x, DA.w), vyP = pk(DA.y, DB.x), vzP = pk(DA.z, DB.y);
    u64 vxQ = pk(DB.z, DC.y), vyQ = pk(DB.w, DC.z), vzQ = pk(DC.x, DC.w);

    float sP0 = 0.f, sP1 = 0.f, sQ0 = 0.f, sQ1 = 0.f;
    float pP0 = 1e30f, pP1 = 1e30f, pQ0 = 1e30f, pQ1 = 1e30f;

    #pragma unroll 1
    for (int blk = 0; blk < N_BLKS; ++blk) {
        #pragma unroll
        for (int u = 0; u < 4; ++u) {
            u64 nP = fma2(qxP, qxP, fma2(qyP, qyP, mul2(qzP, qzP)));
            u64 nQ = fma2(qxQ, qxQ, fma2(qyQ, qyQ, mul2(qzQ, qzQ)));
            float n0, n1; upk(nP, n0, n1);
            sP0 = sqap(n0) - rad;
            sP1 = sqap(n1) - rad;
            float n2, n3; upk(nQ, n2, n3);
            sQ0 = sqap(n2) - rad;
            sQ1 = sqap(n3) - rad;
            u64 s2P = pk(sP0, sP1);
            u64 s2Q = pk(sQ0, sQ1);
            qxP = fma2(s2P, vxP, qxP);
            qyP = fma2(s2P, vyP, qyP);
            qzP = fma2(s2P, vzP, qzP);
            qxQ = fma2(s2Q, vxQ, qxQ);
            qyQ = fma2(s2Q, vyQ, qyQ);
            qzQ = fma2(s2Q, vzQ, qzQ);
        }
        // Per-ray done: converged hit (mask guaranteed 1) or past-perigee miss
        // (mask guaranteed 0). Break only when all 4 rays of this thread are done.
        bool d0 = (sP0 < EPS_HIT) | ((sP0 > pP0) & (sP0 > EPS_MISS));
        bool d1 = (sP1 < EPS_HIT) | ((sP1 > pP1) & (sP1 > EPS_MISS));
        bool d2 = (sQ0 < EPS_HIT) | ((sQ0 > pQ0) & (sQ0 > EPS_MISS));
        bool d3 = (sQ1 < EPS_HIT) | ((sQ1 > pQ1) & (sQ1 > EPS_MISS));
        if (d0 & d1 & d2 & d3) break;
        pP0 = sP0; pP1 = sP1; pQ0 = sQ0; pQ1 = sQ1;
    }
    bool m0 = sP0 < SDF_EPS;
    bool m1 = sP1 < SDF_EPS;
    bool m2 = sQ0 < SDF_EPS;
    bool m3 = sQ1 < SDF_EPS;

    // points = q + center
    u64 cX = pk(cx, cx), cY = pk(cy, cy), cZ = pk(cz, cz);
    u64 pxP = add2(qxP, cX), pyP = add2(qyP, cY), pzP = add2(qzP, cZ);
    u64 pxQ = add2(qxQ, cX), pyQ = add2(qyQ, cY), pzQ = add2(qzQ, cZ);

    float bo0 = b2[0], bo1 = b2[1], bo2 = b2[2];
    u64 a0P = pk(bo0, bo0), a1P = pk(bo1, bo1), a2P = pk(bo2, bo2);
    u64 a0Q = a0P, a1Q = a1P, a2Q = a2P;

    #pragma unroll 8
    for (int j = 0; j < HIDDEN; ++j) {
        ulonglong2 wA = sW1[2 * j];       // {w1x,w1x},{w1y,w1y}
        ulonglong2 wB = sW1[2 * j + 1];   // {w1z,w1z},{b,b}
        u64 hP = fma2(pxP, wA.x, fma2(pyP, wA.y, fma2(pzP, wB.x, wB.y)));
        u64 hQ = fma2(pxQ, wA.x, fma2(pyQ, wA.y, fma2(pzQ, wB.x, wB.y)));
        hP = relu2(hP);
        hQ = relu2(hQ);
        ulonglong2 uA = sW2[2 * j];       // {w20,w20},{w21,w21}
        ulonglong2 uB = sW2[2 * j + 1];   // {w22,w22},{0,0}
        a0P = fma2(hP, uA.x, a0P);
        a1P = fma2(hP, uA.y, a1P);
        a2P = fma2(hP, uB.x, a2P);
        a0Q = fma2(hQ, uA.x, a0Q);
        a1Q = fma2(hQ, uA.y, a1Q);
        a2Q = fma2(hQ, uB.x, a2Q);
    }

    float x00, x10, x01, x11, x02, x12;     // rays 0,1
    upk(a0P, x00, x10); upk(a1P, x01, x11); upk(a2P, x02, x12);
    float x20, x30, x21, x31, x22, x32;     // rays 2,3
    upk(a0Q, x20, x30); upk(a1Q, x21, x31); upk(a2Q, x22, x32);

    float r0c0 = m0 ? sgm(x00) : 0.f, r0c1 = m0 ? sgm(x01) : 0.f, r0c2 = m0 ? sgm(x02) : 0.f;
    float r1c0 = m1 ? sgm(x10) : 0.f, r1c1 = m1 ? sgm(x11) : 0.f, r1c2 = m1 ? sgm(x12) : 0.f;
    float r2c0 = m2 ? sgm(x20) : 0.f, r2c1 = m2 ? sgm(x21) : 0.f, r2c2 = m2 ? sgm(x22) : 0.f;
    float r3c0 = m3 ? sgm(x30) : 0.f, r3c1 = m3 ? sgm(x31) : 0.f, r3c2 = m3 ? sgm(x32) : 0.f;

    float4* o4 = (float4*)out;
    o4[3 * i]     = make_float4(r0c0, r0c1, r0c2, r1c0);
    o4[3 * i + 1] = make_float4(r1c1, r1c2, r2c0, r2c1);
    o4[3 * i + 2] = make_float4(r2c2, r3c0, r3c1, r3c2);
}

extern "C" void kernel_launch(void* const* d_in, const int* in_sizes, int n_in,
                              void* d_out, int out_size) {
    const float* origins    = (const float*)d_in[0];
    const float* directions = (const float*)d_in[1];
    const float* center     = (const float*)d_in[2];
    const float* radius     = (const float*)d_in[3];
    const float* W1         = (const float*)d_in[4];
    const float* b1         = (const float*)d_in[5];
    const float* W2         = (const float*)d_in[6];
    const float* b2         = (const float*)d_in[7];
    float* out = (float*)d_out;

    int n_rays = in_sizes[0] / 3;
    int n_quads = n_rays / 4;
    int block = 256;
    int grid = (n_quads + block - 1) / block;
    sphere_trace_kernel<<<grid, block>>>(origins, directions, center, radius,
                                         W1, b1, W2, b2, out, n_quads);
}